// round 6
// baseline (speedup 1.0000x reference)
#include <cuda_runtime.h>

// Correlation: out[b, di*9+dj, y, x] = (1/64) * sum_c f1[b,c,y,x] * f2pad[b,c,y+di,x+dj]
// f1,f2: [4,64,192,448] f32; out: [4,81,192,448] f32; D=4.
//
// Block (8,4,9)=288 thr; thread owns 4 x-pixels + one di row => 36 accs.
// Stage = 8 channels, 3-deep cp.async ring (dist 2), one barrier per stage (8 total).
// Per channel/thread: 3x LDS.128 window + 1x LDS.128 f1 -> 36 FFMA.

#define D    4
#define CC   64
#define HH   192
#define WW   448
#define BB   4
#define XT   32
#define YT   4
#define XPT  4
#define NTX  8
#define NDJ  9
#define NDI  9
#define PW   (XT + 2*D)      // 40
#define PH   (YT + 2*D)      // 12
#define CS   8               // channels per stage
#define NSTAGE (CC / CS)     // 8
#define NTHREADS (NTX * YT * NDI)  // 288
#define RING 3

#define F2_STAGE_FLOATS (CS*PH*PW)     // 3840
#define F1_STAGE_FLOATS (CS*YT*XT)     // 1024
#define STAGE_FLOATS    (F2_STAGE_FLOATS + F1_STAGE_FLOATS)  // 4864
#define STAGE_BYTES     (STAGE_FLOATS * 4)                   // 19456
#define SMEM_BYTES      (RING * STAGE_BYTES)                 // 58368

#define NCH_F2 (CS*PH*(PW/4))   // 960 16B chunks
#define NCH_F1 (CS*YT*(XT/4))   // 256 16B chunks
#define NCH    (NCH_F2 + NCH_F1) // 1216 = 4*288 + 64
#define CSTRIDE_BYTES ((size_t)CS * HH * WW * 4)   // per-stage channel advance

__device__ __forceinline__ void cp_async16(unsigned saddr, const void* gaddr, int sz) {
    asm volatile("cp.async.cg.shared.global [%0], [%1], 16, %2;"
                 :: "r"(saddr), "l"(gaddr), "r"(sz));
}

__global__ __launch_bounds__(NTHREADS, 3)
void corr_kernel(const float* __restrict__ f1,
                 const float* __restrict__ f2,
                 float* __restrict__ out)
{
    extern __shared__ float smem[];   // RING * STAGE_FLOATS

    const int tx  = threadIdx.x;   // 0..7
    const int ty  = threadIdx.y;   // 0..3
    const int di  = threadIdx.z;   // 0..8
    const int tid = (di * YT + ty) * NTX + tx;

    const int x0 = blockIdx.x * XT;
    const int y0 = blockIdx.y * YT;
    const int b  = blockIdx.z;
    const int y  = y0 + ty;
    const int xp = tx * XPT;

    const float* f1b0 = f1 + (size_t)b * CC * HH * WW;
    const float* f2b0 = f2 + (size_t)b * CC * HH * WW;
    const unsigned sbase = (unsigned)__cvta_generic_to_shared(smem);

    // ---- precompute cp.async chunk descriptors: 4 per thread + 5th for tid<64
    const char* ckp[5];
    unsigned    cks[5];
    int         ckz[5];
    const bool  has5 = (tid < NCH - 4 * NTHREADS);   // tid < 64
#pragma unroll
    for (int k = 0; k < 5; k++) {
        const int c = tid + k * NTHREADS;
        if (k == 4 && !has5) { ckp[k] = (const char*)f1b0; cks[k] = 0; ckz[k] = 0; continue; }
        if (c < NCH_F2) {
            const int cc  = c / (PH * (PW/4));
            const int rem = c - cc * (PH * (PW/4));
            const int r   = rem / (PW/4);
            const int h   = rem - r * (PW/4);
            const int gy  = y0 - D + r;
            const int gxf = x0 - D + h * 4;
            const bool ok = ((unsigned)gy < HH) && ((unsigned)gxf < WW);
            ckp[k] = (const char*)(f2b0 + (size_t)cc * HH * WW
                                  + (ok ? ((size_t)gy * WW + gxf) : 0));
            ckz[k] = ok ? 16 : 0;
            cks[k] = ((cc * PH + r) * PW + h * 4) * 4;
        } else {
            const int c2  = c - NCH_F2;
            const int cc  = c2 / (YT * (XT/4));
            const int rem = c2 - cc * (YT * (XT/4));
            const int r   = rem / (XT/4);
            const int h   = rem - r * (XT/4);
            ckp[k] = (const char*)(f1b0 + (size_t)cc * HH * WW
                                  + (size_t)(y0 + r) * WW + x0 + h * 4);
            ckz[k] = 16;
            cks[k] = F2_STAGE_FLOATS * 4 + ((cc * YT + r) * XT + h * 4) * 4;
        }
    }

    auto prefetch = [&](int s, int buf) {
        if (s < NSTAGE) {
            const size_t gadd = (size_t)s * CSTRIDE_BYTES;
            const unsigned sb = sbase + buf * STAGE_BYTES;
#pragma unroll
            for (int k = 0; k < 4; k++)
                cp_async16(sb + cks[k], ckp[k] + gadd, ckz[k]);
            if (has5) cp_async16(sb + cks[4], ckp[4] + gadd, 16);
        }
        asm volatile("cp.async.commit_group;" ::: "memory");
    };

    float acc[NDJ][XPT];
#pragma unroll
    for (int dj = 0; dj < NDJ; dj++)
#pragma unroll
        for (int xx = 0; xx < XPT; xx++) acc[dj][xx] = 0.f;

    prefetch(0, 0);
    prefetch(1, 1);

    int cb = 0;   // buffer holding stage s
    int pb = 2;   // buffer for stage s+2
    for (int s = 0; s < NSTAGE; s++) {
        asm volatile("cp.async.wait_group 1;" ::: "memory");
        __syncthreads();

        // stage s+2 overwrites buffer of stage s-1, fully consumed by all
        // threads before this barrier. Issue early for full overlap.
        prefetch(s + 2, pb);

        const float* f2t = smem + cb * STAGE_FLOATS;
        const float* f1t = f2t + F2_STAGE_FLOATS;

#pragma unroll
        for (int cc = 0; cc < CS; cc++) {
            const float4 v1 = *(const float4*)&f1t[(cc * YT + ty) * XT + xp];
            const float* wrow = &f2t[(cc * PH + ty + di) * PW + xp];
            float w[12];
            *(float4*)&w[0] = *(const float4*)&wrow[0];
            *(float4*)&w[4] = *(const float4*)&wrow[4];
            *(float4*)&w[8] = *(const float4*)&wrow[8];
#pragma unroll
            for (int dj = 0; dj < NDJ; dj++) {
                acc[dj][0] += v1.x * w[dj + 0];
                acc[dj][1] += v1.y * w[dj + 1];
                acc[dj][2] += v1.z * w[dj + 2];
                acc[dj][3] += v1.w * w[dj + 3];
            }
        }

        cb = (cb == RING - 1) ? 0 : cb + 1;
        pb = (pb == RING - 1) ? 0 : pb + 1;
    }

    const float scale = 1.f / (float)CC;
    float* ob = out + (((size_t)b * (NDI * NDJ) + di * NDJ) * HH + y) * WW + x0 + xp;
#pragma unroll
    for (int dj = 0; dj < NDJ; dj++) {
        float4 o;
        o.x = acc[dj][0] * scale;
        o.y = acc[dj][1] * scale;
        o.z = acc[dj][2] * scale;
        o.w = acc[dj][3] * scale;
        *(float4*)&ob[(size_t)dj * HH * WW] = o;
    }
}

extern "C" void kernel_launch(void* const* d_in, const int* in_sizes, int n_in,
                              void* d_out, int out_size)
{
    const float* f1 = (const float*)d_in[0];
    const float* f2 = (const float*)d_in[1];
    float* out = (float*)d_out;

    cudaFuncSetAttribute(corr_kernel,
                         cudaFuncAttributeMaxDynamicSharedMemorySize, SMEM_BYTES);

    dim3 grid(WW / XT, HH / YT, BB);   // 14 x 48 x 4 = 2688 CTAs
    dim3 block(NTX, YT, NDI);          // 288 threads
    corr_kernel<<<grid, block, SMEM_BYTES>>>(f1, f2, out);
}